// round 1
// baseline (speedup 1.0000x reference)
#include <cuda_runtime.h>
#include <cuda_bf16.h>
#include <cstdint>

// ---------------------------------------------------------------------------
// ConvMultiheadAttention: B=8, S=1024, D=512, H=8, hd=64, KERNEL=3
// out  = [8,1024,512]  (d_out[0 .. 4194304))
// ave  = [8,1024,1024] (d_out[4194304 .. 12582912))
// ---------------------------------------------------------------------------

#define BB 8
#define SS 1024
#define DD 512
#define HH 8
#define HD 64

typedef unsigned long long ull;

// ----- f32x2 helpers (Blackwell packed fp32: 2 FMAs per instruction) -------
__device__ __forceinline__ ull f2fma(ull a, ull b, ull c) {
    ull d; asm("fma.rn.f32x2 %0, %1, %2, %3;" : "=l"(d) : "l"(a), "l"(b), "l"(c)); return d;
}
__device__ __forceinline__ ull f2dup(float x) {
    ull d; asm("mov.b64 %0, {%1, %1};" : "=l"(d) : "f"(x)); return d;
}
__device__ __forceinline__ ull f2add(ull a, ull b) {
    ull d; asm("add.rn.f32x2 %0, %1, %2;" : "=l"(d) : "l"(a), "l"(b)); return d;
}
__device__ __forceinline__ float2 f2unpk(ull a) {
    float2 r; asm("mov.b64 {%0, %1}, %2;" : "=f"(r.x), "=f"(r.y) : "l"(a)); return r;
}

// ----- scratch (static device globals; no runtime allocation) --------------
__device__ float g_xt[3][BB][DD][SS];        // transposed inputs  [B,D,S]  48MB
__device__ float g_qkv[3][BB][DD][SS];       // conv outputs Q,K,V [B,D,S]  48MB
__device__ float g_p[(size_t)BB * HH * SS * SS]; // attention probs       256MB
__device__ float g_o1[BB][SS][DD];           // pre-projection output     16MB

// ---------------------------------------------------------------------------
// Kernel 1: transpose [B,S,D] -> [B,D,S] for q, k, v
// ---------------------------------------------------------------------------
__global__ void transpose_kernel(const float* __restrict__ q,
                                 const float* __restrict__ k,
                                 const float* __restrict__ v) {
    __shared__ float tile[32][33];
    int zz = blockIdx.z;
    int tn = zz / BB, b = zz % BB;
    const float* src = (tn == 0) ? q : (tn == 1) ? k : v;
    float* dst = &g_xt[tn][b][0][0];
    int s0 = blockIdx.x * 32, d0 = blockIdx.y * 32;
    int tx = threadIdx.x, ty = threadIdx.y;
    #pragma unroll
    for (int i = ty; i < 32; i += 8)
        tile[i][tx] = src[((size_t)b * SS + s0 + i) * DD + d0 + tx];
    __syncthreads();
    #pragma unroll
    for (int i = ty; i < 32; i += 8)
        dst[(size_t)(d0 + i) * SS + s0 + tx] = tile[tx][i];
}

// ---------------------------------------------------------------------------
// Kernel 2: conv1d projections as GEMM with on-the-fly im2col.
// out[b,co,s] = sum_{ci,k} W[co,ci,k] * xT[b,ci,s+k-pad] + bias[co]
// Tile 128(co) x 128(s) x 8(kk), 256 threads, 8x8 micro in f32x2.
// ---------------------------------------------------------------------------
__global__ __launch_bounds__(256) void conv_kernel(
    const float* __restrict__ Wq, const float* __restrict__ bq,
    const float* __restrict__ Wk, const float* __restrict__ bk,
    const float* __restrict__ Wv, const float* __restrict__ bv) {
    int zz = blockIdx.z;
    int tn = zz / BB, b = zz % BB;
    const float* W    = (tn == 0) ? Wq : (tn == 1) ? Wk : Wv;
    const float* bias = (tn == 0) ? bq : (tn == 1) ? bk : bv;
    const int KER  = (tn == 2) ? 1 : 3;
    const int Kdim = DD * KER;
    const int pad  = KER >> 1;
    const float* xsrc = &g_xt[tn][b][0][0];
    float* out = &g_qkv[tn][b][0][0];

    __shared__ float As[8][128];
    __shared__ float Bs[8][128];

    const int tid = threadIdx.x;
    const int m0 = blockIdx.x * 128, n0 = blockIdx.y * 128;
    const int tx = tid & 15, ty = tid >> 4;
    const int ai = tid >> 1, aj = (tid & 1) * 4;
    const int bj = tid >> 5, bn = (tid & 31) * 4;

    ull acc[8][4];
    #pragma unroll
    for (int i = 0; i < 8; i++)
        #pragma unroll
        for (int p = 0; p < 4; p++) acc[i][p] = 0ULL;

    for (int kk0 = 0; kk0 < Kdim; kk0 += 8) {
        float4 w = *(const float4*)&W[(size_t)(m0 + ai) * Kdim + kk0 + aj];
        int kk = kk0 + bj;
        int ci, kof;
        if (KER == 3) { ci = kk / 3; kof = kk - ci * 3; }
        else          { ci = kk;     kof = 0; }
        const float* xr = xsrc + (size_t)ci * SS;
        float bv4[4];
        #pragma unroll
        for (int u = 0; u < 4; u++) {
            int t = n0 + bn + u + kof - pad;
            bv4[u] = (t >= 0 && t < SS) ? xr[t] : 0.0f;
        }
        __syncthreads();
        As[aj + 0][ai] = w.x; As[aj + 1][ai] = w.y;
        As[aj + 2][ai] = w.z; As[aj + 3][ai] = w.w;
        #pragma unroll
        for (int u = 0; u < 4; u++) Bs[bj][bn + u] = bv4[u];
        __syncthreads();

        #pragma unroll
        for (int j = 0; j < 8; j++) {
            float4 a0 = *(float4*)&As[j][ty * 8];
            float4 a1 = *(float4*)&As[j][ty * 8 + 4];
            ull b2[4];
            #pragma unroll
            for (int p = 0; p < 4; p++) b2[p] = *(ull*)&Bs[j][tx * 8 + 2 * p];
            float av[8] = {a0.x, a0.y, a0.z, a0.w, a1.x, a1.y, a1.z, a1.w};
            #pragma unroll
            for (int i = 0; i < 8; i++) {
                ull ad = f2dup(av[i]);
                #pragma unroll
                for (int p = 0; p < 4; p++) acc[i][p] = f2fma(ad, b2[p], acc[i][p]);
            }
        }
    }

    #pragma unroll
    for (int i = 0; i < 8; i++) {
        int m = m0 + ty * 8 + i;
        ull bb = f2dup(bias[m]);
        #pragma unroll
        for (int p = 0; p < 4; p++) {
            ull r = f2add(acc[i][p], bb);
            *(ull*)&out[(size_t)m * SS + n0 + tx * 8 + 2 * p] = r;
        }
    }
}

// ---------------------------------------------------------------------------
// Kernel 3: scores + softmax per (b, h, 32-row tile). sc[32][1024] in smem,
// K staged in 64x256 chunks, register-accumulated scores in f32x2,
// full-row softmax, probs written to g_p.
// ---------------------------------------------------------------------------
__global__ __launch_bounds__(256) void scores_kernel() {
    extern __shared__ float sm[];
    float* sc = sm;                    // 32*1024
    float* Kc = sm + 32 * 1024;        // 64*256
    float* Qt = sm + 32 * 1024 + 64 * 256; // 64*32

    const int b = blockIdx.z, h = blockIdx.y, s0 = blockIdx.x * 32;
    const float* Qg = &g_qkv[0][b][h * HD][0];
    const float* Kg = &g_qkv[1][b][h * HD][0];
    const int tid = threadIdx.x;

    #pragma unroll
    for (int i = 0; i < 2; i++) {
        int e = i * 1024 + tid * 4;
        int d = e >> 5, r = e & 31;
        *(float4*)&Qt[d * 32 + r] = *(const float4*)&Qg[(size_t)d * SS + s0 + r];
    }

    const int tx = tid & 63, ty = tid >> 6;
    const int t_l = tx * 4, r_l = ty * 8;

    for (int tc = 0; tc < 4; tc++) {
        __syncthreads();
        #pragma unroll
        for (int i = 0; i < 16; i++) {
            int e = i * 1024 + tid * 4;
            int d = e >> 8, t = e & 255;
            *(float4*)&Kc[d * 256 + t] = *(const float4*)&Kg[(size_t)d * SS + tc * 256 + t];
        }
        __syncthreads();

        ull acc[4][4];
        #pragma unroll
        for (int ri = 0; ri < 4; ri++)
            #pragma unroll
            for (int j = 0; j < 4; j++) acc[ri][j] = 0ULL;

        #pragma unroll
        for (int d = 0; d < 64; d++) {
            const float* qr = &Qt[d * 32 + r_l];
            ull q0 = *(ull*)&qr[0], q1 = *(ull*)&qr[2];
            ull q2 = *(ull*)&qr[4], q3 = *(ull*)&qr[6];
            float4 kv = *(float4*)&Kc[d * 256 + t_l];
            ull k0 = f2dup(kv.x), k1 = f2dup(kv.y);
            ull k2 = f2dup(kv.z), k3 = f2dup(kv.w);
            acc[0][0] = f2fma(q0, k0, acc[0][0]); acc[0][1] = f2fma(q0, k1, acc[0][1]);
            acc[0][2] = f2fma(q0, k2, acc[0][2]); acc[0][3] = f2fma(q0, k3, acc[0][3]);
            acc[1][0] = f2fma(q1, k0, acc[1][0]); acc[1][1] = f2fma(q1, k1, acc[1][1]);
            acc[1][2] = f2fma(q1, k2, acc[1][2]); acc[1][3] = f2fma(q1, k3, acc[1][3]);
            acc[2][0] = f2fma(q2, k0, acc[2][0]); acc[2][1] = f2fma(q2, k1, acc[2][1]);
            acc[2][2] = f2fma(q2, k2, acc[2][2]); acc[2][3] = f2fma(q2, k3, acc[2][3]);
            acc[3][0] = f2fma(q3, k0, acc[3][0]); acc[3][1] = f2fma(q3, k1, acc[3][1]);
            acc[3][2] = f2fma(q3, k2, acc[3][2]); acc[3][3] = f2fma(q3, k3, acc[3][3]);
        }

        const float sclf = 1.0f / 64.0f;
        #pragma unroll
        for (int ri = 0; ri < 4; ri++)
            #pragma unroll
            for (int j = 0; j < 4; j++) {
                float2 v = f2unpk(acc[ri][j]);
                sc[(r_l + 2 * ri) * 1024 + tc * 256 + t_l + j]     = v.x * sclf;
                sc[(r_l + 2 * ri + 1) * 1024 + tc * 256 + t_l + j] = v.y * sclf;
            }
    }
    __syncthreads();

    // softmax: each warp handles 4 rows
    const int warp = tid >> 5, lane = tid & 31;
    for (int rr = warp; rr < 32; rr += 8) {
        float* row = &sc[rr * 1024];
        float m = -1e30f;
        for (int j = lane; j < 1024; j += 32) m = fmaxf(m, row[j]);
        #pragma unroll
        for (int o = 16; o > 0; o >>= 1) m = fmaxf(m, __shfl_xor_sync(0xffffffffu, m, o));
        float s = 0.0f;
        for (int j = lane; j < 1024; j += 32) {
            float e = __expf(row[j] - m);
            row[j] = e;
            s += e;
        }
        #pragma unroll
        for (int o = 16; o > 0; o >>= 1) s += __shfl_xor_sync(0xffffffffu, s, o);
        float inv = 1.0f / s;
        for (int j = lane; j < 1024; j += 32) row[j] *= inv;
    }
    __syncthreads();

    float* Pg = &g_p[(((size_t)(b * HH + h)) << 20) + (size_t)s0 * SS];
    #pragma unroll
    for (int i = 0; i < 32; i++) {
        int e = i * 1024 + tid * 4;
        *(float4*)&Pg[e] = *(float4*)&sc[e];
    }
}

// ---------------------------------------------------------------------------
// Kernel 4: ave_att = mean over heads of P   (deterministic reduction)
// ---------------------------------------------------------------------------
__global__ void ave_kernel(float* __restrict__ ave) {
    size_t idx = (size_t)blockIdx.x * 256 + threadIdx.x;   // < 2097152
    size_t e = idx * 4;
    size_t b = e >> 20, st = e & 1048575;
    float4 a = make_float4(0.f, 0.f, 0.f, 0.f);
    #pragma unroll
    for (int h = 0; h < HH; h++) {
        const float4 p = *(const float4*)&g_p[((b * HH + h) << 20) + st];
        a.x += p.x; a.y += p.y; a.z += p.z; a.w += p.w;
    }
    a.x *= 0.125f; a.y *= 0.125f; a.z *= 0.125f; a.w *= 0.125f;
    *(float4*)&ave[e] = a;
}

// ---------------------------------------------------------------------------
// Kernel 5: PV GEMM per (b,h): out[r,d] = sum_t P[r,t] * V[d,t]
// Tile 128(r) x 64(d) x 16(t), 256 threads, 8x4 micro (r-pairs in f32x2).
// ---------------------------------------------------------------------------
__global__ __launch_bounds__(256) void pv_kernel() {
    __shared__ float As[16][128];   // [t][r]
    __shared__ float Vs[16][64];    // [t][d]
    const int b = blockIdx.z, h = blockIdx.y, s0 = blockIdx.x * 128;
    const float* Pg = &g_p[((size_t)(b * HH + h)) << 20];
    const float* Vg = &g_qkv[2][b][h * HD][0];
    const int tid = threadIdx.x;
    const int tx = tid & 15, ty = tid >> 4;   // d_l = tx*4, r_l = ty*8

    ull acc[4][4];
    #pragma unroll
    for (int ri = 0; ri < 4; ri++)
        #pragma unroll
        for (int j = 0; j < 4; j++) acc[ri][j] = 0ULL;

    for (int t0 = 0; t0 < SS; t0 += 16) {
        int lr = tid >> 1, ltc = (tid & 1) * 8;
        float4 p0 = *(const float4*)&Pg[(size_t)(s0 + lr) * SS + t0 + ltc];
        float4 p1 = *(const float4*)&Pg[(size_t)(s0 + lr) * SS + t0 + ltc + 4];
        int ld = tid >> 2, ltq = (tid & 3) * 4;
        float4 vv = *(const float4*)&Vg[(size_t)ld * SS + t0 + ltq];
        __syncthreads();
        As[ltc + 0][lr] = p0.x; As[ltc + 1][lr] = p0.y;
        As[ltc + 2][lr] = p0.z; As[ltc + 3][lr] = p0.w;
        As[ltc + 4][lr] = p1.x; As[ltc + 5][lr] = p1.y;
        As[ltc + 6][lr] = p1.z; As[ltc + 7][lr] = p1.w;
        Vs[ltq + 0][ld] = vv.x; Vs[ltq + 1][ld] = vv.y;
        Vs[ltq + 2][ld] = vv.z; Vs[ltq + 3][ld] = vv.w;
        __syncthreads();

        #pragma unroll
        for (int kt = 0; kt < 16; kt++) {
            const float* ar = &As[kt][ty * 8];
            ull a0 = *(ull*)&ar[0], a1 = *(ull*)&ar[2];
            ull a2 = *(ull*)&ar[4], a3 = *(ull*)&ar[6];
            float4 v = *(float4*)&Vs[kt][tx * 4];
            ull v0 = f2dup(v.x), v1 = f2dup(v.y), v2 = f2dup(v.z), v3 = f2dup(v.w);
            acc[0][0] = f2fma(a0, v0, acc[0][0]); acc[0][1] = f2fma(a0, v1, acc[0][1]);
            acc[0][2] = f2fma(a0, v2, acc[0][2]); acc[0][3] = f2fma(a0, v3, acc[0][3]);
            acc[1][0] = f2fma(a1, v0, acc[1][0]); acc[1][1] = f2fma(a1, v1, acc[1][1]);
            acc[1][2] = f2fma(a1, v2, acc[1][2]); acc[1][3] = f2fma(a1, v3, acc[1][3]);
            acc[2][0] = f2fma(a2, v0, acc[2][0]); acc[2][1] = f2fma(a2, v1, acc[2][1]);
            acc[2][2] = f2fma(a2, v2, acc[2][2]); acc[2][3] = f2fma(a2, v3, acc[2][3]);
            acc[3][0] = f2fma(a3, v0, acc[3][0]); acc[3][1] = f2fma(a3, v1, acc[3][1]);
            acc[3][2] = f2fma(a3, v2, acc[3][2]); acc[3][3] = f2fma(a3, v3, acc[3][3]);
        }
    }

    float* Og = &g_o1[b][0][0];
    #pragma unroll
    for (int ri = 0; ri < 4; ri++)
        #pragma unroll
        for (int j = 0; j < 4; j++) {
            float2 v = f2unpk(acc[ri][j]);
            int dd = h * HD + tx * 4 + j;
            Og[(size_t)(s0 + ty * 8 + 2 * ri) * DD + dd]     = v.x;
            Og[(size_t)(s0 + ty * 8 + 2 * ri + 1) * DD + dd] = v.y;
        }
}

// ---------------------------------------------------------------------------
// Kernel 6: output projection: out = O1 @ Wo^T + bo
// M=8192, N=512, K=512. Tile 128x128x8, 8x8 micro in f32x2.
// ---------------------------------------------------------------------------
__global__ __launch_bounds__(256) void proj_kernel(const float* __restrict__ Wo,
                                                   const float* __restrict__ bo,
                                                   float* __restrict__ out) {
    __shared__ float As[8][128];
    __shared__ float Bs[8][128];
    const int m0 = blockIdx.x * 128, n0 = blockIdx.y * 128;
    const float* A = &g_o1[0][0][0];
    const int tid = threadIdx.x, tx = tid & 15, ty = tid >> 4;
    const int li = tid >> 1, lj = (tid & 1) * 4;

    ull acc[8][4];
    #pragma unroll
    for (int i = 0; i < 8; i++)
        #pragma unroll
        for (int p = 0; p < 4; p++) acc[i][p] = 0ULL;

    for (int k0 = 0; k0 < DD; k0 += 8) {
        float4 av = *(const float4*)&A[(size_t)(m0 + li) * DD + k0 + lj];
        float4 bv = *(const float4*)&Wo[(size_t)(n0 + li) * DD + k0 + lj];
        __syncthreads();
        As[lj + 0][li] = av.x; As[lj + 1][li] = av.y;
        As[lj + 2][li] = av.z; As[lj + 3][li] = av.w;
        Bs[lj + 0][li] = bv.x; Bs[lj + 1][li] = bv.y;
        Bs[lj + 2][li] = bv.z; Bs[lj + 3][li] = bv.w;
        __syncthreads();

        #pragma unroll
        for (int j = 0; j < 8; j++) {
            float4 a0 = *(float4*)&As[j][ty * 8];
            float4 a1 = *(float4*)&As[j][ty * 8 + 4];
            ull b2[4];
            #pragma unroll
            for (int p = 0; p < 4; p++) b2[p] = *(ull*)&Bs[j][tx * 8 + 2 * p];
            float avv[8] = {a0.x, a0.y, a0.z, a0.w, a1.x, a1.y, a1.z, a1.w};
            #pragma unroll
            for (int i = 0; i < 8; i++) {
                ull ad = f2dup(avv[i]);
                #pragma unroll
                for (int p = 0; p < 4; p++) acc[i][p] = f2fma(ad, b2[p], acc[i][p]);
            }
        }
    }

    #pragma unroll
    for (int i = 0; i < 8; i++) {
        int m = m0 + ty * 8 + i;
        #pragma unroll
        for (int p = 0; p < 4; p++) {
            ull bb = *(const ull*)&bo[n0 + tx * 8 + 2 * p];
            ull r = f2add(acc[i][p], bb);
            *(ull*)&out[(size_t)m * DD + n0 + tx * 8 + 2 * p] = r;
        }
    }
}

// ---------------------------------------------------------------------------
extern "C" void kernel_launch(void* const* d_in, const int* in_sizes, int n_in,
                              void* d_out, int out_size) {
    const float* query = (const float*)d_in[0];
    const float* key_t = (const float*)d_in[1];
    const float* value = (const float*)d_in[2];
    const float* Wq    = (const float*)d_in[3];
    const float* bq    = (const float*)d_in[4];
    const float* Wk    = (const float*)d_in[5];
    const float* bk    = (const float*)d_in[6];
    const float* Wv    = (const float*)d_in[7];
    const float* bv    = (const float*)d_in[8];
    const float* Wo    = (const float*)d_in[9];
    const float* bo    = (const float*)d_in[10];

    float* out = (float*)d_out;
    float* ave = out + (size_t)BB * SS * DD;

    const size_t SC_SMEM = (size_t)(32 * 1024 + 64 * 256 + 64 * 32) * sizeof(float);
    cudaFuncSetAttribute(scores_kernel, cudaFuncAttributeMaxDynamicSharedMemorySize,
                         (int)SC_SMEM);

    transpose_kernel<<<dim3(SS / 32, DD / 32, 3 * BB), dim3(32, 8)>>>(query, key_t, value);
    conv_kernel<<<dim3(DD / 128, SS / 128, 3 * BB), 256>>>(Wq, bq, Wk, bk, Wv, bv);
    scores_kernel<<<dim3(SS / 32, HH, BB), 256, SC_SMEM>>>();
    pv_kernel<<<dim3(SS / 128, HH, BB), 256>>>();
    ave_kernel<<<(BB * SS * SS / 4) / 256, 256>>>(ave);
    proj_kernel<<<dim3((BB * SS) / 128, DD / 128), 256>>>(Wo, bo, out);
}